// round 6
// baseline (speedup 1.0000x reference)
#include <cuda_runtime.h>

#define NN 10000     // nodes
#define KD 8         // out-degree
#define EE 80000     // edges
#define HDIM 512     // H*D
#define NPB 4        // nodes per block in node_edge

// Scratch (allocation-free rule: __device__ globals)
__device__ float g_nq[NN * HDIM];
__device__ float g_nk[NN * HDIM];
__device__ float g_nv[NN * HDIM];
__device__ float g_attn[NN * 64];     // [n][j*8+h] node-softmax weights

// ---- packed f32x2 helpers (FFMA2 path: only reachable via PTX) ----
__device__ __forceinline__ unsigned long long pack2(float lo, float hi) {
    unsigned long long r;
    asm("mov.b64 %0, {%1, %2};" : "=l"(r) : "f"(lo), "f"(hi));
    return r;
}
__device__ __forceinline__ void ffma2(unsigned long long& d,
                                      unsigned long long a,
                                      unsigned long long b) {
    asm("fma.rn.f32x2 %0, %1, %2, %0;" : "+l"(d) : "l"(a), "l"(b));
}
__device__ __forceinline__ float2 unpack2(unsigned long long v) {
    float2 f;
    asm("mov.b64 {%0, %1}, %2;" : "=f"(f.x), "=f"(f.y) : "l"(v));
    return f;
}

// group barrier: named bar per 64-thread node group (ids 1..NPB)
#define GBAR(s) asm volatile("bar.sync %0, %1;" :: "r"((s)+1), "r"(64) : "memory")

// ---------------------------------------------------------------------------
// Kernel 1: fused QKV projection.  out = X[10000,64] @ W^T[64,512] + b.
// 128 threads, 64x128 tile, 8x8 microtile, f32x2 packed FMA.
// ---------------------------------------------------------------------------
__global__ __launch_bounds__(128) void proj_qkv_kernel(
    const float* __restrict__ X,
    const float* __restrict__ Wq, const float* __restrict__ bq,
    const float* __restrict__ Wk, const float* __restrict__ bk,
    const float* __restrict__ Wv, const float* __restrict__ bv)
{
    __shared__ float As[64][68];     // [row][k]
    __shared__ float Bs[64][132];    // [k][col]

    int bx  = blockIdx.x;
    int sel = bx >> 2;
    int c0  = (bx & 3) * 128;
    int r0  = blockIdx.y * 64;
    int t   = threadIdx.x;

    const float* W    = (sel == 0) ? Wq : (sel == 1) ? Wk : Wv;
    const float* bias = (sel == 0) ? bq : (sel == 1) ? bk : bv;
    float*       outp = (sel == 0) ? g_nq : (sel == 1) ? g_nk : g_nv;

    #pragma unroll
    for (int i = 0; i < 8; i++) {
        int idx = t + i * 128;
        int row = idx >> 4, k4 = idx & 15;
        float4 v = make_float4(0.f, 0.f, 0.f, 0.f);
        if (r0 + row < NN) v = *(const float4*)&X[(r0 + row) * 64 + k4 * 4];
        *(float4*)&As[row][k4 * 4] = v;
    }
    #pragma unroll
    for (int i = 0; i < 16; i++) {
        int idx = t + i * 128;
        int c = idx >> 4, k4 = idx & 15;
        float4 w = *(const float4*)&W[(c0 + c) * 64 + k4 * 4];
        Bs[k4*4+0][c] = w.x; Bs[k4*4+1][c] = w.y;
        Bs[k4*4+2][c] = w.z; Bs[k4*4+3][c] = w.w;
    }
    __syncthreads();

    int tx = t & 15, ty = t >> 4;
    unsigned long long acc[8][4] = {};

    #pragma unroll
    for (int k0 = 0; k0 < 64; k0 += 4) {
        float4 a4[8];
        #pragma unroll
        for (int i = 0; i < 8; i++) a4[i] = *(const float4*)&As[ty * 8 + i][k0];
        #pragma unroll
        for (int kk = 0; kk < 4; kk++) {
            unsigned long long b[4];
            #pragma unroll
            for (int p = 0; p < 4; p++)
                b[p] = *reinterpret_cast<const unsigned long long*>(&Bs[k0 + kk][tx * 2 + 32 * p]);
            #pragma unroll
            for (int i = 0; i < 8; i++) {
                float av = ((const float*)&a4[i])[kk];
                unsigned long long a = pack2(av, av);
                #pragma unroll
                for (int p = 0; p < 4; p++)
                    ffma2(acc[i][p], a, b[p]);
            }
        }
    }

    float2 bb[4];
    #pragma unroll
    for (int p = 0; p < 4; p++) {
        int c = c0 + tx * 2 + 32 * p;
        bb[p] = make_float2(bias[c], bias[c + 1]);
    }
    #pragma unroll
    for (int i = 0; i < 8; i++) {
        int row = r0 + ty * 8 + i;
        if (row < NN) {
            #pragma unroll
            for (int p = 0; p < 4; p++) {
                int c = c0 + tx * 2 + 32 * p;
                float2 r = unpack2(acc[i][p]);
                *(float2*)&outp[(long)row * HDIM + c] =
                    make_float2(r.x + bb[p].x, r.y + bb[p].y);
            }
        }
    }
}

// ---------------------------------------------------------------------------
// Kernel 2: fused per-node pipeline (ends at the node softmax; aggregation
// moved into out_gemm). 4 nodes/block, 64 threads per node group.
// ---------------------------------------------------------------------------
__global__ __launch_bounds__(256) void node_edge_kernel(
    const float* __restrict__ edge_features,
    const int*   __restrict__ edge_index,
    const float* __restrict__ Weq, const float* __restrict__ beq,
    const float* __restrict__ Wev, const float* __restrict__ bev,
    const float* __restrict__ Wek, const float* __restrict__ bek,
    const float* __restrict__ Wel, const float* __restrict__ bel,
    const float* __restrict__ Wele, const float* __restrict__ bele,
    float* __restrict__ out_edge)
{
    // weights staged once per block
    __shared__ float s_Weq[64][17];
    __shared__ float s_Wev[64][17];
    __shared__ float s_Wek[64][9];
    __shared__ __align__(16) float s_Wel[8][68];
    __shared__ float s_Wele[16][9];
    // per-node state
    __shared__ __align__(16) float s_ef[NPB][8][16];
    __shared__ __align__(16) float s_sqk[NPB][8][8];
    __shared__ __align__(16) float s_eqS[NPB][8][68];   // eq, reused as eout
    __shared__ __align__(16) float s_evS[NPB][8][68];
    __shared__ __align__(16) float s_ekS[NPB][8][68];
    __shared__ __align__(16) float s_att[NPB][8][4][8];
    __shared__ float s_ee[NPB][8][9];
    __shared__ float s_attn[NPB][8][9];

    int t    = threadIdx.x;
    int sub  = t >> 6;
    int u    = t & 63;
    int lane = u & 31;
    int w2   = u >> 5;
    int n    = blockIdx.x * NPB + sub;

    // ---- stage weights (cooperative, whole block) ----
    for (int i = t; i < 1024; i += 256) {
        s_Weq[i >> 4][i & 15] = Weq[i];
        s_Wev[i >> 4][i & 15] = Wev[i];
    }
    for (int i = t; i < 512; i += 256) {
        s_Wek[i >> 3][i & 7]  = Wek[i];
        s_Wel[i >> 6][i & 63] = Wel[i];
    }
    if (t < 128) s_Wele[t >> 3][t & 7] = Wele[t];

    // ---- e1 via warp shuffle ----
    int ej = (lane < 8) ? edge_index[EE + n * 8 + lane] : 0;
    int e1r[8];
    #pragma unroll
    for (int j = 0; j < 8; j++) e1r[j] = __shfl_sync(0xffffffffu, ej, j);

    // ---- edge features ----
    if (u < 32) ((float4*)&s_ef[sub][0][0])[u] =
                    ((const float4*)(edge_features + (long)n * 128))[u];

    // ---- phase 1: sqk[j][h] = <nq[n,h,:], nk[e1[j],h,:]> / 8 ----
    {
        float4 q4[4];
        const float4* qp = (const float4*)(g_nq + (long)n * 512);
        #pragma unroll
        for (int i = 0; i < 4; i++) q4[i] = qp[lane + 32 * i];
        #pragma unroll
        for (int jj = 0; jj < 4; jj++) {
            int j = w2 * 4 + jj;
            const float4* kp = (const float4*)(g_nk + (long)e1r[j] * 512);
            float p[4];
            #pragma unroll
            for (int i = 0; i < 4; i++) {
                float4 kv = __ldg(&kp[lane + 32 * i]);
                p[i] = q4[i].x * kv.x + q4[i].y * kv.y + q4[i].z * kv.z + q4[i].w * kv.w;
            }
            #pragma unroll
            for (int m = 1; m < 16; m <<= 1)
                #pragma unroll
                for (int i = 0; i < 4; i++)
                    p[i] += __shfl_xor_sync(0xffffffffu, p[i], m);
            if ((lane & 15) == 0) {
                int hp = lane >> 4;
                #pragma unroll
                for (int i = 0; i < 4; i++)
                    s_sqk[sub][j][2 * i + hp] = p[i] * 0.125f;
            }
        }
    }
    __syncthreads();   // weights + s_ef + s_sqk all visible

    // ---- phase 2: eq/ev/ek projections. thread u owns output column u ----
    {
        float wq[16], wv[16], wk8[8];
        #pragma unroll
        for (int c = 0; c < 16; c++) { wq[c] = s_Weq[u][c]; wv[c] = s_Wev[u][c]; }
        #pragma unroll
        for (int c = 0; c < 8; c++) wk8[c] = s_Wek[u][c];
        float bq_ = beq[u], bv_ = bev[u], bk_ = bek[u];
        #pragma unroll
        for (int j = 0; j < 8; j++) {
            const float4* ef4 = (const float4*)&s_ef[sub][j][0];
            const float4* sq4 = (const float4*)&s_sqk[sub][j][0];
            float aq = bq_, av = bv_, ak = bk_;
            #pragma unroll
            for (int c4 = 0; c4 < 4; c4++) {
                float4 f = ef4[c4];
                aq = fmaf(f.x, wq[c4*4+0], aq); aq = fmaf(f.y, wq[c4*4+1], aq);
                aq = fmaf(f.z, wq[c4*4+2], aq); aq = fmaf(f.w, wq[c4*4+3], aq);
                av = fmaf(f.x, wv[c4*4+0], av); av = fmaf(f.y, wv[c4*4+1], av);
                av = fmaf(f.z, wv[c4*4+2], av); av = fmaf(f.w, wv[c4*4+3], av);
            }
            #pragma unroll
            for (int c4 = 0; c4 < 2; c4++) {
                float4 s = sq4[c4];
                ak = fmaf(s.x, wk8[c4*4+0], ak); ak = fmaf(s.y, wk8[c4*4+1], ak);
                ak = fmaf(s.z, wk8[c4*4+2], ak); ak = fmaf(s.w, wk8[c4*4+3], ak);
            }
            s_eqS[sub][j][u] = aq;
            s_evS[sub][j][u] = av;
            s_ekS[sub][j][u] = ak;
        }
    }
    GBAR(sub);

    // ---- phase 3: edge-edge attention. thread u = (q=u>>3, k=u&7) ----
    {
        int q = u >> 3, k = u & 7;
        const float4* eq4 = (const float4*)&s_eqS[sub][q][0];
        const float4* ek4 = (const float4*)&s_ekS[sub][k][0];
        #pragma unroll
        for (int eh = 0; eh < 4; eh++) {
            float s = 0.f;
            #pragma unroll
            for (int c = 0; c < 4; c++) {
                float4 a = eq4[eh * 4 + c];
                float4 b = ek4[eh * 4 + c];
                s += a.x * b.x + a.y * b.y + a.z * b.z + a.w * b.w;
            }
            s *= 0.25f;
            float mx = s;
            mx = fmaxf(mx, __shfl_xor_sync(0xffffffffu, mx, 1));
            mx = fmaxf(mx, __shfl_xor_sync(0xffffffffu, mx, 2));
            mx = fmaxf(mx, __shfl_xor_sync(0xffffffffu, mx, 4));
            float ex = expf(s - mx);
            float sm = ex;
            sm += __shfl_xor_sync(0xffffffffu, sm, 1);
            sm += __shfl_xor_sync(0xffffffffu, sm, 2);
            sm += __shfl_xor_sync(0xffffffffu, sm, 4);
            s_att[sub][q][eh][k] = ex / (sm + 1e-16f);
        }
    }
    GBAR(sub);

    // ---- phase 4: eout[q][u] = sum_k att[q][eh(u)][k] * ev[k][u] (into eqS) ----
    {
        int eh = u >> 4;
        float ev[8];
        #pragma unroll
        for (int k = 0; k < 8; k++) ev[k] = s_evS[sub][k][u];
        #pragma unroll
        for (int q = 0; q < 8; q++) {
            float4 a0 = *(const float4*)&s_att[sub][q][eh][0];
            float4 a1 = *(const float4*)&s_att[sub][q][eh][4];
            float acc = 0.f;
            acc = fmaf(a0.x, ev[0], acc); acc = fmaf(a0.y, ev[1], acc);
            acc = fmaf(a0.z, ev[2], acc); acc = fmaf(a0.w, ev[3], acc);
            acc = fmaf(a1.x, ev[4], acc); acc = fmaf(a1.y, ev[5], acc);
            acc = fmaf(a1.z, ev[6], acc); acc = fmaf(a1.w, ev[7], acc);
            s_eqS[sub][q][u] = acc;
        }
    }
    GBAR(sub);

    // ---- phase 5: edge_emb[q][h] ----
    {
        int q = u >> 3, h = u & 7;
        float acc = bel[h];
        const float4* e4 = (const float4*)&s_eqS[sub][q][0];
        const float4* w4 = (const float4*)&s_Wel[h][0];
        #pragma unroll
        for (int c = 0; c < 16; c++) {
            float4 e = e4[c], w = w4[c];
            acc += e.x * w.x + e.y * w.y + e.z * w.z + e.w * w.w;
        }
        s_ee[sub][q][h] = acc;
    }
    GBAR(sub);

    // ---- phase 6a: node softmax (u<8); 6b: edge_embeddings output ----
    if (u < 8) {
        int h = u;
        float l[8], mx = -1e30f;
        #pragma unroll
        for (int j = 0; j < 8; j++) {
            l[j] = s_ee[sub][j][h] + s_sqk[sub][j][h];
            mx = fmaxf(mx, l[j]);
        }
        float sm = 0.f;
        #pragma unroll
        for (int j = 0; j < 8; j++) { l[j] = expf(l[j] - mx); sm += l[j]; }
        float inv = 1.f / (sm + 1e-16f);
        #pragma unroll
        for (int j = 0; j < 8; j++) s_attn[sub][j][h] = l[j] * inv;
    }
    {
        int q = u >> 3, d2 = (u & 7) * 2;
        float a0 = bele[d2], a1 = bele[d2 + 1];
        #pragma unroll
        for (int h = 0; h < 8; h++) {
            float e = s_ee[sub][q][h];
            a0 = fmaf(e, s_Wele[d2][h], a0);
            a1 = fmaf(e, s_Wele[d2 + 1][h], a1);
        }
        *(float2*)&out_edge[(n * 8 + q) * 16 + d2] = make_float2(a0, a1);
    }
    GBAR(sub);

    // ---- export node attention weights: g_attn[n][j*8+h] ----
    g_attn[(long)n * 64 + u] = s_attn[sub][u >> 3][u & 7];
}

// ---------------------------------------------------------------------------
// Kernel 3 (fused): node_embeddings = (Σ_j attn·nv[e1]) @ Wlin^T + blin.
// Per 64-col k-slab the head h = k0g/64 is constant, so the A-tile is built
// by gathering nv directly — g_node never materializes. attn scalars are
// read straight from g_attn (L2-resident, tiny).
// ---------------------------------------------------------------------------
__global__ __launch_bounds__(256) void out_gemm_kernel(
    const float* __restrict__ Wlin, const float* __restrict__ blin,
    const int*   __restrict__ edge_index,
    float* __restrict__ out)
{
    __shared__ __align__(16) float As[64][68];
    __shared__ float Ws[64][66];
    __shared__ int   s_e1[64][8];

    int r0 = blockIdx.x * 64;
    int t  = threadIdx.x;

    // load e1 block [64 nodes x 8]
    #pragma unroll
    for (int i = 0; i < 2; i++) {
        int idx = t + i * 256;
        int row = idx >> 3, j = idx & 7;
        s_e1[row][j] = (r0 + row < NN) ? edge_index[EE + (r0 + row) * 8 + j] : 0;
    }
    __syncthreads();

    int tx = t & 15, ty = t >> 4;
    unsigned long long acc[4][2] = {};

    int grow = t >> 2;              // gather: 4 threads per row
    int gc   = (t & 3) * 16;        // 16-col chunk

    // hoist edge targets for this thread's row
    int e1g[8];
    #pragma unroll
    for (int j = 0; j < 8; j++) e1g[j] = s_e1[grow][j];
    bool rowok = (r0 + grow) < NN;

    for (int k0g = 0; k0g < 512; k0g += 64) {
        int h = k0g >> 6;
        // ---- build A-tile by gathering nv, weighted by attn ----
        float4 A0 = {0,0,0,0}, A1 = {0,0,0,0}, A2 = {0,0,0,0}, A3 = {0,0,0,0};
        if (rowok) {
            #pragma unroll
            for (int j = 0; j < 8; j++) {
                float w = __ldg(&g_attn[(long)(r0 + grow) * 64 + j * 8 + h]);
                const float4* vp = (const float4*)(g_nv + (long)e1g[j] * 512 + k0g + gc);
                float4 v0 = __ldg(&vp[0]), v1 = __ldg(&vp[1]);
                float4 v2 = __ldg(&vp[2]), v3 = __ldg(&vp[3]);
                A0.x = fmaf(w, v0.x, A0.x); A0.y = fmaf(w, v0.y, A0.y);
                A0.z = fmaf(w, v0.z, A0.z); A0.w = fmaf(w, v0.w, A0.w);
                A1.x = fmaf(w, v1.x, A1.x); A1.y = fmaf(w, v1.y, A1.y);
                A1.z = fmaf(w, v1.z, A1.z); A1.w = fmaf(w, v1.w, A1.w);
                A2.x = fmaf(w, v2.x, A2.x); A2.y = fmaf(w, v2.y, A2.y);
                A2.z = fmaf(w, v2.z, A2.z); A2.w = fmaf(w, v2.w, A2.w);
                A3.x = fmaf(w, v3.x, A3.x); A3.y = fmaf(w, v3.y, A3.y);
                A3.z = fmaf(w, v3.z, A3.z); A3.w = fmaf(w, v3.w, A3.w);
            }
        }
        *(float4*)&As[grow][gc + 0]  = A0;
        *(float4*)&As[grow][gc + 4]  = A1;
        *(float4*)&As[grow][gc + 8]  = A2;
        *(float4*)&As[grow][gc + 12] = A3;

        // ---- load Wlin slab transposed into Ws[k][d]: 64 d x 64 k ----
        #pragma unroll
        for (int i = 0; i < 4; i++) {
            int idx = t + i * 256;
            int row = idx >> 4, k4 = idx & 15;       // row = out dim d
            float4 w = *(const float4*)&Wlin[(long)row * 512 + k0g + k4 * 4];
            Ws[k4*4+0][row] = w.x; Ws[k4*4+1][row] = w.y;
            Ws[k4*4+2][row] = w.z; Ws[k4*4+3][row] = w.w;
        }
        __syncthreads();

        // ---- GEMM on the slab ----
        #pragma unroll
        for (int k0 = 0; k0 < 64; k0 += 4) {
            float4 a4[4];
            #pragma unroll
            for (int i = 0; i < 4; i++) a4[i] = *(const float4*)&As[ty * 4 + i][k0];
            #pragma unroll
            for (int kk = 0; kk < 4; kk++) {
                unsigned long long b[2];
                #pragma unroll
                for (int p = 0; p < 2; p++)
                    b[p] = *reinterpret_cast<const unsigned long long*>(&Ws[k0 + kk][tx * 2 + 32 * p]);
                #pragma unroll
                for (int i = 0; i < 4; i++) {
                    float av = ((const float*)&a4[i])[kk];
                    unsigned long long a = pack2(av, av);
                    #pragma unroll
                    for (int p = 0; p < 2; p++)
                        ffma2(acc[i][p], a, b[p]);
                }
            }
        }
        __syncthreads();
    }

    #pragma unroll
    for (int i = 0; i < 4; i++) {
        int row = r0 + ty * 4 + i;
        if (row < NN) {
            #pragma unroll
            for (int p = 0; p < 2; p++) {
                int d = tx * 2 + 32 * p;
                float2 r = unpack2(acc[i][p]);
                *(float2*)&out[(long)row * 64 + d] =
                    make_float2(r.x + blin[d], r.y + blin[d + 1]);
            }
        }
    }
}

// ---------------------------------------------------------------------------
extern "C" void kernel_launch(void* const* d_in, const int* in_sizes, int n_in,
                              void* d_out, int out_size)
{
    const float* x    = (const float*)d_in[0];
    const float* ef   = (const float*)d_in[1];
    const float* Wq   = (const float*)d_in[2];
    const float* bq   = (const float*)d_in[3];
    const float* Wk   = (const float*)d_in[4];
    const float* bk   = (const float*)d_in[5];
    const float* Wv   = (const float*)d_in[6];
    const float* bv   = (const float*)d_in[7];
    const float* Wlin = (const float*)d_in[8];
    const float* blin = (const float*)d_in[9];
    const float* Weq  = (const float*)d_in[10];
    const float* beq  = (const float*)d_in[11];
    const float* Wev  = (const float*)d_in[12];
    const float* bev  = (const float*)d_in[13];
    const float* Wek  = (const float*)d_in[14];
    const float* bek  = (const float*)d_in[15];
    const float* Wel  = (const float*)d_in[16];
    const float* bel  = (const float*)d_in[17];
    const float* Wele = (const float*)d_in[18];
    const float* bele = (const float*)d_in[19];
    const int*   eidx = (const int*)d_in[20];
    float* out = (float*)d_out;

    proj_qkv_kernel<<<dim3(12, 157), 128>>>(x, Wq, bq, Wk, bk, Wv, bv);
    node_edge_kernel<<<NN / NPB, 256>>>(ef, eidx, Weq, beq, Wev, bev, Wek, bek,
                                        Wel, bel, Wele, bele, out + NN * 64);
    out_gemm_kernel<<<157, 256>>>(Wlin, blin, eidx, out);
}

// round 7
// speedup vs baseline: 1.1605x; 1.1605x over previous
#include <cuda_runtime.h>

#define NN 10000     // nodes
#define KD 8         // out-degree
#define EE 80000     // edges
#define HDIM 512     // H*D

// Scratch (allocation-free rule: __device__ globals)
__device__ float g_nq[NN * HDIM];
__device__ float g_nk[NN * HDIM];
__device__ float g_nv[NN * HDIM];
__device__ float g_node[NN * HDIM];

// ---- packed f32x2 helpers (FFMA2 path: only reachable via PTX) ----
__device__ __forceinline__ unsigned long long pack2(float lo, float hi) {
    unsigned long long r;
    asm("mov.b64 %0, {%1, %2};" : "=l"(r) : "f"(lo), "f"(hi));
    return r;
}
__device__ __forceinline__ void ffma2(unsigned long long& d,
                                      unsigned long long a,
                                      unsigned long long b) {
    asm("fma.rn.f32x2 %0, %1, %2, %0;" : "+l"(d) : "l"(a), "l"(b));
}
__device__ __forceinline__ float2 unpack2(unsigned long long v) {
    float2 f;
    asm("mov.b64 {%0, %1}, %2;" : "=f"(f.x), "=f"(f.y) : "l"(v));
    return f;
}

// ---------------------------------------------------------------------------
// Kernel 1: fused QKV projection.  out = X[10000,64] @ W^T[64,512] + b.
// 128 threads, 64x128 tile, 8x8 microtile, f32x2 packed FMA.  (R4, unchanged)
// ---------------------------------------------------------------------------
__global__ __launch_bounds__(128) void proj_qkv_kernel(
    const float* __restrict__ X,
    const float* __restrict__ Wq, const float* __restrict__ bq,
    const float* __restrict__ Wk, const float* __restrict__ bk,
    const float* __restrict__ Wv, const float* __restrict__ bv)
{
    __shared__ float As[64][68];     // [row][k]
    __shared__ float Bs[64][132];    // [k][col]

    int bx  = blockIdx.x;
    int sel = bx >> 2;
    int c0  = (bx & 3) * 128;
    int r0  = blockIdx.y * 64;
    int t   = threadIdx.x;

    const float* W    = (sel == 0) ? Wq : (sel == 1) ? Wk : Wv;
    const float* bias = (sel == 0) ? bq : (sel == 1) ? bk : bv;
    float*       outp = (sel == 0) ? g_nq : (sel == 1) ? g_nk : g_nv;

    #pragma unroll
    for (int i = 0; i < 8; i++) {
        int idx = t + i * 128;
        int row = idx >> 4, k4 = idx & 15;
        float4 v = make_float4(0.f, 0.f, 0.f, 0.f);
        if (r0 + row < NN) v = *(const float4*)&X[(r0 + row) * 64 + k4 * 4];
        *(float4*)&As[row][k4 * 4] = v;
    }
    #pragma unroll
    for (int i = 0; i < 16; i++) {
        int idx = t + i * 128;
        int c = idx >> 4, k4 = idx & 15;
        float4 w = *(const float4*)&W[(c0 + c) * 64 + k4 * 4];
        Bs[k4*4+0][c] = w.x; Bs[k4*4+1][c] = w.y;
        Bs[k4*4+2][c] = w.z; Bs[k4*4+3][c] = w.w;
    }
    __syncthreads();

    int tx = t & 15, ty = t >> 4;
    unsigned long long acc[8][4] = {};

    #pragma unroll
    for (int k0 = 0; k0 < 64; k0 += 4) {
        float4 a4[8];
        #pragma unroll
        for (int i = 0; i < 8; i++) a4[i] = *(const float4*)&As[ty * 8 + i][k0];
        #pragma unroll
        for (int kk = 0; kk < 4; kk++) {
            unsigned long long b[4];
            #pragma unroll
            for (int p = 0; p < 4; p++)
                b[p] = *reinterpret_cast<const unsigned long long*>(&Bs[k0 + kk][tx * 2 + 32 * p]);
            #pragma unroll
            for (int i = 0; i < 8; i++) {
                float av = ((const float*)&a4[i])[kk];
                unsigned long long a = pack2(av, av);
                #pragma unroll
                for (int p = 0; p < 4; p++)
                    ffma2(acc[i][p], a, b[p]);
            }
        }
    }

    float2 bb[4];
    #pragma unroll
    for (int p = 0; p < 4; p++) {
        int c = c0 + tx * 2 + 32 * p;
        bb[p] = make_float2(bias[c], bias[c + 1]);
    }
    #pragma unroll
    for (int i = 0; i < 8; i++) {
        int row = r0 + ty * 8 + i;
        if (row < NN) {
            #pragma unroll
            for (int p = 0; p < 4; p++) {
                int c = c0 + tx * 2 + 32 * p;
                float2 r = unpack2(acc[i][p]);
                *(float2*)&outp[(long)row * HDIM + c] =
                    make_float2(r.x + bb[p].x, r.y + bb[p].y);
            }
        }
    }
}

// ---------------------------------------------------------------------------
// Kernel 2: warp-per-node fused pipeline. 4 warps/block = 4 nodes/block.
// No named barriers; one __syncthreads (weight staging); __syncwarp between
// phases. All smem rows padded to 68 floats (bank stride 4 per row).
// ---------------------------------------------------------------------------
__global__ __launch_bounds__(128) void node_edge_kernel(
    const float* __restrict__ edge_features,
    const int*   __restrict__ edge_index,
    const float* __restrict__ Weq, const float* __restrict__ beq,
    const float* __restrict__ Wev, const float* __restrict__ bev,
    const float* __restrict__ Wek, const float* __restrict__ bek,
    const float* __restrict__ Wel, const float* __restrict__ bel,
    const float* __restrict__ Wele, const float* __restrict__ bele,
    float* __restrict__ out_edge)
{
    // block-shared weights (transposed for pair loads)
    __shared__ float s_WeqT[16][64];              // [c][u]
    __shared__ float s_WevT[16][64];
    __shared__ float s_WekT[8][64];
    __shared__ __align__(16) float s_Wel[8][68];  // [h][c]
    __shared__ float s_Wele[16][9];               // [de][h]
    // per-node (warp-private) state
    __shared__ __align__(16) float s_ef[4][8][16];
    __shared__ __align__(16) float s_eq[4][8][68];   // eq, reused as eout
    __shared__ __align__(16) float s_ev[4][8][68];
    __shared__ __align__(16) float s_ek[4][8][68];
    __shared__ __align__(16) float s_att[4][8][4][8];
    __shared__ float s_sqk[4][8][8];
    __shared__ float s_ee[4][8][8];
    __shared__ float s_attn[4][8][8];

    int t    = threadIdx.x;
    int nd   = t >> 5;
    int lane = t & 31;
    int n    = blockIdx.x * 4 + nd;

    // ---- stage weights (whole block, conflict-free STS) ----
    for (int i = t; i < 1024; i += 128) {
        int u = i & 63, c = i >> 6;
        s_WeqT[c][u] = Weq[u * 16 + c];
        s_WevT[c][u] = Wev[u * 16 + c];
    }
    for (int i = t; i < 512; i += 128) {
        int u = i & 63, c = i >> 6;
        s_WekT[c][u] = Wek[u * 8 + c];
    }
    for (int i = t; i < 512; i += 128) {
        int h = i >> 6, c = i & 63;
        s_Wel[h][c] = Wel[i];
    }
    s_Wele[t >> 3][t & 7] = Wele[t];   // t < 128 always

    // ---- e1 via warp shuffle ----
    int ej = (lane < 8) ? edge_index[EE + n * 8 + lane] : 0;
    int e1r[8];
    #pragma unroll
    for (int j = 0; j < 8; j++) e1r[j] = __shfl_sync(0xffffffffu, ej, j);

    // ---- edge features (128 floats per node, one float4 per lane) ----
    ((float4*)&s_ef[nd][0][0])[lane] =
        ((const float4*)(edge_features + (long)n * 128))[lane];

    // ---- phase 1: sqk[j][h] = <nq[n,h,:], nk[e1[j],h,:]> / 8 ----
    {
        const float4* qp = (const float4*)(g_nq + (long)n * 512);
        float4 q4[4];
        #pragma unroll
        for (int i = 0; i < 4; i++) q4[i] = qp[lane + 32 * i];
        #pragma unroll
        for (int j = 0; j < 8; j++) {
            const float4* kp = (const float4*)(g_nk + (long)e1r[j] * 512);
            float p[4];
            #pragma unroll
            for (int i = 0; i < 4; i++) {
                float4 kv = __ldg(&kp[lane + 32 * i]);
                p[i] = q4[i].x * kv.x + q4[i].y * kv.y + q4[i].z * kv.z + q4[i].w * kv.w;
            }
            #pragma unroll
            for (int m = 1; m < 16; m <<= 1)
                #pragma unroll
                for (int i = 0; i < 4; i++)
                    p[i] += __shfl_xor_sync(0xffffffffu, p[i], m);
            if ((lane & 15) == 0) {
                int hp = lane >> 4;
                #pragma unroll
                for (int i = 0; i < 4; i++)
                    s_sqk[nd][j][2 * i + hp] = p[i] * 0.125f;
            }
        }
    }
    __syncthreads();    // weights visible; warp-private state already ordered

    // ---- phase 2: eq/ev/ek. lane owns columns u0=2*lane, u0+1 (f32x2) ----
    {
        int u0 = 2 * lane;
        unsigned long long aq[8], av[8], ak[8];
        float2 b2;
        b2 = *(const float2*)&beq[u0];
        unsigned long long bq2 = pack2(b2.x, b2.y);
        b2 = *(const float2*)&bev[u0];
        unsigned long long bv2 = pack2(b2.x, b2.y);
        b2 = *(const float2*)&bek[u0];
        unsigned long long bk2 = pack2(b2.x, b2.y);
        #pragma unroll
        for (int j = 0; j < 8; j++) { aq[j] = bq2; av[j] = bv2; ak[j] = bk2; }
        #pragma unroll
        for (int c = 0; c < 16; c++) {
            unsigned long long wq = *reinterpret_cast<const unsigned long long*>(&s_WeqT[c][u0]);
            unsigned long long wv = *reinterpret_cast<const unsigned long long*>(&s_WevT[c][u0]);
            #pragma unroll
            for (int j = 0; j < 8; j++) {
                float f = s_ef[nd][j][c];
                unsigned long long f2 = pack2(f, f);
                ffma2(aq[j], f2, wq);
                ffma2(av[j], f2, wv);
            }
        }
        #pragma unroll
        for (int c = 0; c < 8; c++) {
            unsigned long long wk = *reinterpret_cast<const unsigned long long*>(&s_WekT[c][u0]);
            #pragma unroll
            for (int j = 0; j < 8; j++) {
                float s = s_sqk[nd][j][c];
                ffma2(ak[j], pack2(s, s), wk);
            }
        }
        #pragma unroll
        for (int j = 0; j < 8; j++) {
            *(float2*)&s_eq[nd][j][u0] = unpack2(aq[j]);
            *(float2*)&s_ev[nd][j][u0] = unpack2(av[j]);
            *(float2*)&s_ek[nd][j][u0] = unpack2(ak[j]);
        }
    }
    __syncwarp();

    // ---- phase 3: edge-edge attention. 2 (q,k) pairs per lane ----
    #pragma unroll
    for (int rep = 0; rep < 2; rep++) {
        int p = lane + 32 * rep;
        int q = p >> 3, k = p & 7;
        const float4* eqp = (const float4*)&s_eq[nd][q][0];
        const float4* ekp = (const float4*)&s_ek[nd][k][0];
        #pragma unroll
        for (int eh = 0; eh < 4; eh++) {
            float s = 0.f;
            #pragma unroll
            for (int c = 0; c < 4; c++) {
                float4 a = eqp[eh * 4 + c];
                float4 b = ekp[eh * 4 + c];
                s += a.x * b.x + a.y * b.y + a.z * b.z + a.w * b.w;
            }
            s *= 0.25f;
            float mx = s;
            mx = fmaxf(mx, __shfl_xor_sync(0xffffffffu, mx, 1));
            mx = fmaxf(mx, __shfl_xor_sync(0xffffffffu, mx, 2));
            mx = fmaxf(mx, __shfl_xor_sync(0xffffffffu, mx, 4));
            float ex = expf(s - mx);
            float sm = ex;
            sm += __shfl_xor_sync(0xffffffffu, sm, 1);
            sm += __shfl_xor_sync(0xffffffffu, sm, 2);
            sm += __shfl_xor_sync(0xffffffffu, sm, 4);
            s_att[nd][q][eh][k] = ex / (sm + 1e-16f);
        }
    }
    __syncwarp();

    // ---- phase 4: eout[q][u] = sum_k att[q][eh(u)][k] * ev[k][u] ----
    #pragma unroll
    for (int rep = 0; rep < 2; rep++) {
        int u = lane + 32 * rep;
        int eh = u >> 4;
        float evr[8];
        #pragma unroll
        for (int k = 0; k < 8; k++) evr[k] = s_ev[nd][k][u];
        #pragma unroll
        for (int q = 0; q < 8; q++) {
            float4 a0 = *(const float4*)&s_att[nd][q][eh][0];
            float4 a1 = *(const float4*)&s_att[nd][q][eh][4];
            float acc = 0.f;
            acc = fmaf(a0.x, evr[0], acc); acc = fmaf(a0.y, evr[1], acc);
            acc = fmaf(a0.z, evr[2], acc); acc = fmaf(a0.w, evr[3], acc);
            acc = fmaf(a1.x, evr[4], acc); acc = fmaf(a1.y, evr[5], acc);
            acc = fmaf(a1.z, evr[6], acc); acc = fmaf(a1.w, evr[7], acc);
            s_eq[nd][q][u] = acc;          // eq reused as eout
        }
    }
    __syncwarp();

    // ---- phase 5: edge_emb[q][h] = eout[q] . Wel[h] + bel[h] ----
    #pragma unroll
    for (int rep = 0; rep < 2; rep++) {
        int p = lane + 32 * rep;
        int q = p >> 3, h = p & 7;
        float acc = bel[h];
        const float4* ep = (const float4*)&s_eq[nd][q][0];
        const float4* wp = (const float4*)&s_Wel[h][0];
        #pragma unroll
        for (int c = 0; c < 16; c++) {
            float4 e = ep[c], w = wp[c];
            acc += e.x * w.x + e.y * w.y + e.z * w.z + e.w * w.w;
        }
        s_ee[nd][q][h] = acc;
    }
    __syncwarp();

    // ---- phase 6a: node softmax (lanes 0-7) ----
    if (lane < 8) {
        int h = lane;
        float l[8], mx = -1e30f;
        #pragma unroll
        for (int j = 0; j < 8; j++) {
            l[j] = s_ee[nd][j][h] + s_sqk[nd][j][h];
            mx = fmaxf(mx, l[j]);
        }
        float sm = 0.f;
        #pragma unroll
        for (int j = 0; j < 8; j++) { l[j] = expf(l[j] - mx); sm += l[j]; }
        float inv = 1.f / (sm + 1e-16f);
        #pragma unroll
        for (int j = 0; j < 8; j++) s_attn[nd][j][h] = l[j] * inv;
    }
    // ---- phase 6b: edge_embeddings output ----
    #pragma unroll
    for (int rep = 0; rep < 2; rep++) {
        int p = lane + 32 * rep;
        int q = p >> 3, d2 = (p & 7) * 2;
        float a0 = bele[d2], a1 = bele[d2 + 1];
        #pragma unroll
        for (int h = 0; h < 8; h++) {
            float e = s_ee[nd][q][h];
            a0 = fmaf(e, s_Wele[d2][h], a0);
            a1 = fmaf(e, s_Wele[d2 + 1][h], a1);
        }
        *(float2*)&out_edge[(n * 8 + q) * 16 + d2] = make_float2(a0, a1);
    }
    __syncwarp();

    // ---- phase 7: node aggregation into g_node ----
    #pragma unroll
    for (int i = 0; i < 4; i++) {
        int c4 = lane + 32 * i;            // float4 column index
        int h  = c4 >> 4;
        float4 acc = make_float4(0.f, 0.f, 0.f, 0.f);
        #pragma unroll
        for (int j = 0; j < 8; j++) {
            float w = s_attn[nd][j][h];
            float4 v = __ldg((const float4*)(g_nv + (long)e1r[j] * 512) + c4);
            acc.x = fmaf(w, v.x, acc.x); acc.y = fmaf(w, v.y, acc.y);
            acc.z = fmaf(w, v.z, acc.z); acc.w = fmaf(w, v.w, acc.w);
        }
        ((float4*)(g_node + (long)n * 512))[c4] = acc;
    }
}

// ---------------------------------------------------------------------------
// Kernel 3: node_embeddings = g_node[10000,512] @ Wlin^T[512,64] + blin (R4)
// ---------------------------------------------------------------------------
__global__ __launch_bounds__(256) void out_gemm_kernel(
    const float* __restrict__ Wlin, const float* __restrict__ blin,
    float* __restrict__ out)
{
    __shared__ float As[64][68];
    __shared__ float Ws[64][66];
    int r0 = blockIdx.x * 64;
    int t  = threadIdx.x;
    int tx = t & 15, ty = t >> 4;
    unsigned long long acc[4][2] = {};

    for (int k0g = 0; k0g < 512; k0g += 64) {
        __syncthreads();
        #pragma unroll
        for (int i = 0; i < 4; i++) {
            int idx = t + i * 256;
            int row = idx >> 4, k4 = idx & 15;
            float4 v = make_float4(0.f, 0.f, 0.f, 0.f);
            if (r0 + row < NN) v = *(const float4*)&g_node[(long)(r0 + row) * 512 + k0g + k4 * 4];
            *(float4*)&As[row][k4 * 4] = v;
            float4 w = *(const float4*)&Wlin[(long)row * 512 + k0g + k4 * 4];
            Ws[k4*4+0][row] = w.x; Ws[k4*4+1][row] = w.y;
            Ws[k4*4+2][row] = w.z; Ws[k4*4+3][row] = w.w;
        }
        __syncthreads();
        #pragma unroll
        for (int k0 = 0; k0 < 64; k0 += 4) {
            float4 a4[4];
            #pragma unroll
            for (int i = 0; i < 4; i++) a4[i] = *(const float4*)&As[ty * 4 + i][k0];
            #pragma unroll
            for (int kk = 0; kk < 4; kk++) {
                unsigned long long b[2];
                #pragma unroll
                for (int p = 0; p < 2; p++)
                    b[p] = *reinterpret_cast<const unsigned long long*>(&Ws[k0 + kk][tx * 2 + 32 * p]);
                #pragma unroll
                for (int i = 0; i < 4; i++) {
                    float av = ((const float*)&a4[i])[kk];
                    unsigned long long a = pack2(av, av);
                    #pragma unroll
                    for (int p = 0; p < 2; p++)
                        ffma2(acc[i][p], a, b[p]);
                }
            }
        }
    }

    #pragma unroll
    for (int i = 0; i < 4; i++) {
        int row = r0 + ty * 4 + i;
        if (row < NN) {
            #pragma unroll
            for (int p = 0; p < 2; p++) {
                int d = tx * 2 + 32 * p;
                float2 r = unpack2(acc[i][p]);
                *(float2*)&out[(long)row * 64 + d] =
                    make_float2(r.x + blin[d], r.y + blin[d + 1]);
            }
        }
    }
}

// ---------------------------------------------------------------------------
extern "C" void kernel_launch(void* const* d_in, const int* in_sizes, int n_in,
                              void* d_out, int out_size)
{
    const float* x    = (const float*)d_in[0];
    const float* ef   = (const float*)d_in[1];
    const float* Wq   = (const float*)d_in[2];
    const float* bq   = (const float*)d_in[3];
    const float* Wk   = (const float*)d_in[4];
    const float* bk   = (const float*)d_in[5];
    const float* Wv   = (const float*)d_in[6];
    const float* bv   = (const float*)d_in[7];
    const float* Wlin = (const float*)d_in[8];
    const float* blin = (const float*)d_in[9];
    const float* Weq  = (const float*)d_in[10];
    const float* beq  = (const float*)d_in[11];
    const float* Wev  = (const float*)d_in[12];
    const float* bev  = (const float*)d_in[13];
    const float* Wek  = (const float*)d_in[14];
    const float* bek  = (const float*)d_in[15];
    const float* Wel  = (const float*)d_in[16];
    const float* bel  = (const float*)d_in[17];
    const float* Wele = (const float*)d_in[18];
    const float* bele = (const float*)d_in[19];
    const int*   eidx = (const int*)d_in[20];
    float* out = (float*)d_out;

    proj_qkv_kernel<<<dim3(12, 157), 128>>>(x, Wq, bq, Wk, bk, Wv, bv);
    node_edge_kernel<<<NN / 4, 128>>>(ef, eidx, Weq, beq, Wev, bev, Wek, bek,
                                      Wel, bel, Wele, bele, out + NN * 64);
    out_gemm_kernel<<<157, 256>>>(Wlin, blin, out);
}

// round 8
// speedup vs baseline: 1.1760x; 1.0134x over previous
#include <cuda_runtime.h>

#define NN 10000     // nodes
#define KD 8         // out-degree
#define EE 80000     // edges
#define HDIM 512     // H*D

// Scratch (allocation-free rule: __device__ globals)
__device__ float g_nq[NN * HDIM];
__device__ float g_nk[NN * HDIM];
__device__ float g_nv[NN * HDIM];
__device__ float g_node[NN * HDIM];

// ---- packed f32x2 helpers (FFMA2 path: only reachable via PTX) ----
__device__ __forceinline__ unsigned long long pack2(float lo, float hi) {
    unsigned long long r;
    asm("mov.b64 %0, {%1, %2};" : "=l"(r) : "f"(lo), "f"(hi));
    return r;
}
__device__ __forceinline__ void ffma2(unsigned long long& d,
                                      unsigned long long a,
                                      unsigned long long b) {
    asm("fma.rn.f32x2 %0, %1, %2, %0;" : "+l"(d) : "l"(a), "l"(b));
}
__device__ __forceinline__ float2 unpack2(unsigned long long v) {
    float2 f;
    asm("mov.b64 {%0, %1}, %2;" : "=f"(f.x), "=f"(f.y) : "l"(v));
    return f;
}
__device__ __forceinline__ float f4c(const float4& v, int i) {
    return (i == 0) ? v.x : (i == 1) ? v.y : (i == 2) ? v.z : v.w;
}

// ---------------------------------------------------------------------------
// Kernel 1: fused QKV projection (R4, unchanged).
// ---------------------------------------------------------------------------
__global__ __launch_bounds__(128) void proj_qkv_kernel(
    const float* __restrict__ X,
    const float* __restrict__ Wq, const float* __restrict__ bq,
    const float* __restrict__ Wk, const float* __restrict__ bk,
    const float* __restrict__ Wv, const float* __restrict__ bv)
{
    __shared__ float As[64][68];     // [row][k]
    __shared__ float Bs[64][132];    // [k][col]

    int bx  = blockIdx.x;
    int sel = bx >> 2;
    int c0  = (bx & 3) * 128;
    int r0  = blockIdx.y * 64;
    int t   = threadIdx.x;

    const float* W    = (sel == 0) ? Wq : (sel == 1) ? Wk : Wv;
    const float* bias = (sel == 0) ? bq : (sel == 1) ? bk : bv;
    float*       outp = (sel == 0) ? g_nq : (sel == 1) ? g_nk : g_nv;

    #pragma unroll
    for (int i = 0; i < 8; i++) {
        int idx = t + i * 128;
        int row = idx >> 4, k4 = idx & 15;
        float4 v = make_float4(0.f, 0.f, 0.f, 0.f);
        if (r0 + row < NN) v = *(const float4*)&X[(r0 + row) * 64 + k4 * 4];
        *(float4*)&As[row][k4 * 4] = v;
    }
    #pragma unroll
    for (int i = 0; i < 16; i++) {
        int idx = t + i * 128;
        int c = idx >> 4, k4 = idx & 15;
        float4 w = *(const float4*)&W[(c0 + c) * 64 + k4 * 4];
        Bs[k4*4+0][c] = w.x; Bs[k4*4+1][c] = w.y;
        Bs[k4*4+2][c] = w.z; Bs[k4*4+3][c] = w.w;
    }
    __syncthreads();

    int tx = t & 15, ty = t >> 4;
    unsigned long long acc[8][4] = {};

    #pragma unroll
    for (int k0 = 0; k0 < 64; k0 += 4) {
        float4 a4[8];
        #pragma unroll
        for (int i = 0; i < 8; i++) a4[i] = *(const float4*)&As[ty * 8 + i][k0];
        #pragma unroll
        for (int kk = 0; kk < 4; kk++) {
            unsigned long long b[4];
            #pragma unroll
            for (int p = 0; p < 4; p++)
                b[p] = *reinterpret_cast<const unsigned long long*>(&Bs[k0 + kk][tx * 2 + 32 * p]);
            #pragma unroll
            for (int i = 0; i < 8; i++) {
                float av = ((const float*)&a4[i])[kk];
                unsigned long long a = pack2(av, av);
                #pragma unroll
                for (int p = 0; p < 4; p++)
                    ffma2(acc[i][p], a, b[p]);
            }
        }
    }

    float2 bb[4];
    #pragma unroll
    for (int p = 0; p < 4; p++) {
        int c = c0 + tx * 2 + 32 * p;
        bb[p] = make_float2(bias[c], bias[c + 1]);
    }
    #pragma unroll
    for (int i = 0; i < 8; i++) {
        int row = r0 + ty * 8 + i;
        if (row < NN) {
            #pragma unroll
            for (int p = 0; p < 4; p++) {
                int c = c0 + tx * 2 + 32 * p;
                float2 r = unpack2(acc[i][p]);
                *(float2*)&outp[(long)row * HDIM + c] =
                    make_float2(r.x + bb[p].x, r.y + bb[p].y);
            }
        }
    }
}

// ---------------------------------------------------------------------------
// Kernel 2: warp-per-node fused pipeline, smem diet (no Weq/Wev/Wek staging,
// per-lane weight-row LDGs), head-aligned phase-1 reduction.
// ---------------------------------------------------------------------------
__global__ __launch_bounds__(128) void node_edge_kernel(
    const float* __restrict__ edge_features,
    const int*   __restrict__ edge_index,
    const float* __restrict__ Weq, const float* __restrict__ beq,
    const float* __restrict__ Wev, const float* __restrict__ bev,
    const float* __restrict__ Wek, const float* __restrict__ bek,
    const float* __restrict__ Wel, const float* __restrict__ bel,
    const float* __restrict__ Wele, const float* __restrict__ bele,
    float* __restrict__ out_edge)
{
    __shared__ __align__(16) float s_Wel[8][68];  // [h][c]
    __shared__ float s_Wele[16][9];               // [de][h]
    // per-node (warp-private) state
    __shared__ __align__(16) float s_ef[4][8][16];
    __shared__ __align__(16) float s_eq[4][8][68];   // eq, reused as eout
    __shared__ __align__(16) float s_ev[4][8][68];
    __shared__ __align__(16) float s_ek[4][8][68];
    __shared__ __align__(16) float s_att[4][8][4][8];
    __shared__ float s_sqk[4][8][8];
    __shared__ float s_ee[4][8][8];
    __shared__ float s_attn[4][8][8];

    int t    = threadIdx.x;
    int nd   = t >> 5;
    int lane = t & 31;
    int n    = blockIdx.x * 4 + nd;

    // ---- stage small weights (block-coop) ----
    for (int i = t; i < 512; i += 128) s_Wel[i >> 6][i & 63] = Wel[i];
    s_Wele[t >> 3][t & 7] = Wele[t];   // t < 128
    __syncthreads();

    // ---- e1 via warp shuffle ----
    int ej = (lane < 8) ? edge_index[EE + n * 8 + lane] : 0;
    int e1r[8];
    #pragma unroll
    for (int j = 0; j < 8; j++) e1r[j] = __shfl_sync(0xffffffffu, ej, j);

    // ---- edge features (128 floats, one float4 per lane) ----
    ((float4*)&s_ef[nd][0][0])[lane] =
        ((const float4*)(edge_features + (long)n * 128))[lane];

    // ---- phase 1: sqk[j][h] head-aligned; 4 lanes per head, 2 shuffles ----
    {
        int hh = lane >> 2, mm = lane & 3;
        const float4* qp = (const float4*)(g_nq + (long)n * 512);
        float4 q4[4];
        #pragma unroll
        for (int i = 0; i < 4; i++) q4[i] = qp[hh * 16 + mm + 4 * i];
        #pragma unroll
        for (int j = 0; j < 8; j++) {
            const float4* kp = (const float4*)(g_nk + (long)e1r[j] * 512);
            float s = 0.f;
            #pragma unroll
            for (int i = 0; i < 4; i++) {
                float4 kv = __ldg(&kp[hh * 16 + mm + 4 * i]);
                s += q4[i].x * kv.x + q4[i].y * kv.y + q4[i].z * kv.z + q4[i].w * kv.w;
            }
            s += __shfl_xor_sync(0xffffffffu, s, 1);
            s += __shfl_xor_sync(0xffffffffu, s, 2);
            if (mm == 0) s_sqk[nd][j][hh] = s * 0.125f;
        }
    }
    __syncwarp();

    // ---- phase 2: eq/ev/ek. lane owns cols uA=lane, uB=lane+32 (f32x2) ----
    {
        int uA = lane, uB = lane + 32;
        // eq/ev
        unsigned long long aq[8], av[8];
        {
            unsigned long long bq2 = pack2(__ldg(&beq[uA]), __ldg(&beq[uB]));
            unsigned long long bv2 = pack2(__ldg(&bev[uA]), __ldg(&bev[uB]));
            #pragma unroll
            for (int j = 0; j < 8; j++) { aq[j] = bq2; av[j] = bv2; }
        }
        #pragma unroll
        for (int c4 = 0; c4 < 4; c4++) {
            float4 wqA = __ldg((const float4*)Weq + uA * 4 + c4);
            float4 wqB = __ldg((const float4*)Weq + uB * 4 + c4);
            float4 wvA = __ldg((const float4*)Wev + uA * 4 + c4);
            float4 wvB = __ldg((const float4*)Wev + uB * 4 + c4);
            #pragma unroll
            for (int cc = 0; cc < 4; cc++) {
                int c = c4 * 4 + cc;
                unsigned long long wq2 = pack2(f4c(wqA, cc), f4c(wqB, cc));
                unsigned long long wv2 = pack2(f4c(wvA, cc), f4c(wvB, cc));
                #pragma unroll
                for (int j = 0; j < 8; j++) {
                    float f = s_ef[nd][j][c];
                    unsigned long long f2 = pack2(f, f);
                    ffma2(aq[j], f2, wq2);
                    ffma2(av[j], f2, wv2);
                }
            }
        }
        #pragma unroll
        for (int j = 0; j < 8; j++) {
            float2 q2 = unpack2(aq[j]);
            float2 v2 = unpack2(av[j]);
            s_eq[nd][j][uA] = q2.x; s_eq[nd][j][uB] = q2.y;
            s_ev[nd][j][uA] = v2.x; s_ev[nd][j][uB] = v2.y;
        }
        // ek (in = 8 sqk heads)
        unsigned long long ak[8];
        {
            unsigned long long bk2 = pack2(__ldg(&bek[uA]), __ldg(&bek[uB]));
            #pragma unroll
            for (int j = 0; j < 8; j++) ak[j] = bk2;
        }
        #pragma unroll
        for (int c2 = 0; c2 < 2; c2++) {
            float4 wkA = __ldg((const float4*)Wek + uA * 2 + c2);
            float4 wkB = __ldg((const float4*)Wek + uB * 2 + c2);
            #pragma unroll
            for (int cc = 0; cc < 4; cc++) {
                int c = c2 * 4 + cc;
                unsigned long long wk2 = pack2(f4c(wkA, cc), f4c(wkB, cc));
                #pragma unroll
                for (int j = 0; j < 8; j++) {
                    float s = s_sqk[nd][j][c];
                    ffma2(ak[j], pack2(s, s), wk2);
                }
            }
        }
        #pragma unroll
        for (int j = 0; j < 8; j++) {
            float2 k2 = unpack2(ak[j]);
            s_ek[nd][j][uA] = k2.x; s_ek[nd][j][uB] = k2.y;
        }
    }
    __syncwarp();

    // ---- phase 3: edge-edge attention. 2 (q,k) pairs per lane ----
    #pragma unroll
    for (int rep = 0; rep < 2; rep++) {
        int p = lane + 32 * rep;
        int q = p >> 3, k = p & 7;
        const float4* eqp = (const float4*)&s_eq[nd][q][0];
        const float4* ekp = (const float4*)&s_ek[nd][k][0];
        #pragma unroll
        for (int eh = 0; eh < 4; eh++) {
            float s = 0.f;
            #pragma unroll
            for (int c = 0; c < 4; c++) {
                float4 a = eqp[eh * 4 + c];
                float4 b = ekp[eh * 4 + c];
                s += a.x * b.x + a.y * b.y + a.z * b.z + a.w * b.w;
            }
            s *= 0.25f;
            float mx = s;
            mx = fmaxf(mx, __shfl_xor_sync(0xffffffffu, mx, 1));
            mx = fmaxf(mx, __shfl_xor_sync(0xffffffffu, mx, 2));
            mx = fmaxf(mx, __shfl_xor_sync(0xffffffffu, mx, 4));
            float ex = expf(s - mx);
            float sm = ex;
            sm += __shfl_xor_sync(0xffffffffu, sm, 1);
            sm += __shfl_xor_sync(0xffffffffu, sm, 2);
            sm += __shfl_xor_sync(0xffffffffu, sm, 4);
            s_att[nd][q][eh][k] = ex / (sm + 1e-16f);
        }
    }
    __syncwarp();

    // ---- phase 4: eout[q][u] = sum_k att[q][eh(u)][k] * ev[k][u] ----
    #pragma unroll
    for (int rep = 0; rep < 2; rep++) {
        int u = lane + 32 * rep;
        int eh = u >> 4;
        float evr[8];
        #pragma unroll
        for (int k = 0; k < 8; k++) evr[k] = s_ev[nd][k][u];
        #pragma unroll
        for (int q = 0; q < 8; q++) {
            float4 a0 = *(const float4*)&s_att[nd][q][eh][0];
            float4 a1 = *(const float4*)&s_att[nd][q][eh][4];
            float acc = 0.f;
            acc = fmaf(a0.x, evr[0], acc); acc = fmaf(a0.y, evr[1], acc);
            acc = fmaf(a0.z, evr[2], acc); acc = fmaf(a0.w, evr[3], acc);
            acc = fmaf(a1.x, evr[4], acc); acc = fmaf(a1.y, evr[5], acc);
            acc = fmaf(a1.z, evr[6], acc); acc = fmaf(a1.w, evr[7], acc);
            s_eq[nd][q][u] = acc;          // eq reused as eout
        }
    }
    __syncwarp();

    // ---- phase 5: edge_emb[q][h] = eout[q] . Wel[h] + bel[h] ----
    #pragma unroll
    for (int rep = 0; rep < 2; rep++) {
        int p = lane + 32 * rep;
        int q = p >> 3, h = p & 7;
        float acc = __ldg(&bel[h]);
        const float4* ep = (const float4*)&s_eq[nd][q][0];
        const float4* wp = (const float4*)&s_Wel[h][0];
        #pragma unroll
        for (int c = 0; c < 16; c++) {
            float4 e = ep[c], w = wp[c];
            acc += e.x * w.x + e.y * w.y + e.z * w.z + e.w * w.w;
        }
        s_ee[nd][q][h] = acc;
    }
    __syncwarp();

    // ---- phase 6a: node softmax (lanes 0-7) ----
    if (lane < 8) {
        int h = lane;
        float l[8], mx = -1e30f;
        #pragma unroll
        for (int j = 0; j < 8; j++) {
            l[j] = s_ee[nd][j][h] + s_sqk[nd][j][h];
            mx = fmaxf(mx, l[j]);
        }
        float sm = 0.f;
        #pragma unroll
        for (int j = 0; j < 8; j++) { l[j] = expf(l[j] - mx); sm += l[j]; }
        float inv = 1.f / (sm + 1e-16f);
        #pragma unroll
        for (int j = 0; j < 8; j++) s_attn[nd][j][h] = l[j] * inv;
    }
    // ---- phase 6b: edge_embeddings output ----
    #pragma unroll
    for (int rep = 0; rep < 2; rep++) {
        int p = lane + 32 * rep;
        int q = p >> 3, d2 = (p & 7) * 2;
        float a0 = __ldg(&bele[d2]), a1 = __ldg(&bele[d2 + 1]);
        #pragma unroll
        for (int h = 0; h < 8; h++) {
            float e = s_ee[nd][q][h];
            a0 = fmaf(e, s_Wele[d2][h], a0);
            a1 = fmaf(e, s_Wele[d2 + 1][h], a1);
        }
        *(float2*)&out_edge[(n * 8 + q) * 16 + d2] = make_float2(a0, a1);
    }
    __syncwarp();

    // ---- phase 7: node aggregation into g_node ----
    #pragma unroll
    for (int i = 0; i < 4; i++) {
        int c4 = lane + 32 * i;            // float4 column index
        int h  = c4 >> 4;
        float4 acc = make_float4(0.f, 0.f, 0.f, 0.f);
        #pragma unroll
        for (int j = 0; j < 8; j++) {
            float w = s_attn[nd][j][h];
            float4 v = __ldg((const float4*)(g_nv + (long)e1r[j] * 512) + c4);
            acc.x = fmaf(w, v.x, acc.x); acc.y = fmaf(w, v.y, acc.y);
            acc.z = fmaf(w, v.z, acc.z); acc.w = fmaf(w, v.w, acc.w);
        }
        ((float4*)(g_node + (long)n * 512))[c4] = acc;
    }
}

// ---------------------------------------------------------------------------
// Kernel 3: node_embeddings = g_node[10000,512] @ Wlin^T[512,64] + blin (R4)
// ---------------------------------------------------------------------------
__global__ __launch_bounds__(256) void out_gemm_kernel(
    const float* __restrict__ Wlin, const float* __restrict__ blin,
    float* __restrict__ out)
{
    __shared__ float As[64][68];
    __shared__ float Ws[64][66];
    int r0 = blockIdx.x * 64;
    int t  = threadIdx.x;
    int tx = t & 15, ty = t >> 4;
    unsigned long long acc[4][2] = {};

    for (int k0g = 0; k0g < 512; k0g += 64) {
        __syncthreads();
        #pragma unroll
        for (int i = 0; i < 4; i++) {
            int idx = t + i * 256;
            int row = idx >> 4, k4 = idx & 15;
            float4 v = make_float4(0.f, 0.f, 0.f, 0.f);
            if (r0 + row < NN) v = *(const float4*)&g_node[(long)(r0 + row) * 512 + k0g + k4 * 4];
            *(float4*)&As[row][k4 * 4] = v;
            float4 w = *(const float4*)&Wlin[(long)row * 512 + k0g + k4 * 4];
            Ws[k4*4+0][row] = w.x; Ws[k4*4+1][row] = w.y;
            Ws[k4*4+2][row] = w.z; Ws[k4*4+3][row] = w.w;
        }
        __syncthreads();
        #pragma unroll
        for (int k0 = 0; k0 < 64; k0 += 4) {
            float4 a4[4];
            #pragma unroll
            for (int i = 0; i < 4; i++) a4[i] = *(const float4*)&As[ty * 4 + i][k0];
            #pragma unroll
            for (int kk = 0; kk < 4; kk++) {
                unsigned long long b[2];
                #pragma unroll
                for (int p = 0; p < 2; p++)
                    b[p] = *reinterpret_cast<const unsigned long long*>(&Ws[k0 + kk][tx * 2 + 32 * p]);
                #pragma unroll
                for (int i = 0; i < 4; i++) {
                    float av = ((const float*)&a4[i])[kk];
                    unsigned long long a = pack2(av, av);
                    #pragma unroll
                    for (int p = 0; p < 2; p++)
                        ffma2(acc[i][p], a, b[p]);
                }
            }
        }
    }

    #pragma unroll
    for (int i = 0; i < 4; i++) {
        int row = r0 + ty * 4 + i;
        if (row < NN) {
            #pragma unroll
            for (int p = 0; p < 2; p++) {
                int d = tx * 2 + 32 * p;
                float2 r = unpack2(acc[i][p]);
                *(float2*)&out[(long)row * 64 + d] =
                    make_float2(r.x + blin[d], r.y + blin[d + 1]);
            }
        }
    }
}

// ---------------------------------------------------------------------------
extern "C" void kernel_launch(void* const* d_in, const int* in_sizes, int n_in,
                              void* d_out, int out_size)
{
    const float* x    = (const float*)d_in[0];
    const float* ef   = (const float*)d_in[1];
    const float* Wq   = (const float*)d_in[2];
    const float* bq   = (const float*)d_in[3];
    const float* Wk   = (const float*)d_in[4];
    const float* bk   = (const float*)d_in[5];
    const float* Wv   = (const float*)d_in[6];
    const float* bv   = (const float*)d_in[7];
    const float* Wlin = (const float*)d_in[8];
    const float* blin = (const float*)d_in[9];
    const float* Weq  = (const float*)d_in[10];
    const float* beq  = (const float*)d_in[11];
    const float* Wev  = (const float*)d_in[12];
    const float* bev  = (const float*)d_in[13];
    const float* Wek  = (const float*)d_in[14];
    const float* bek  = (const float*)d_in[15];
    const float* Wel  = (const float*)d_in[16];
    const float* bel  = (const float*)d_in[17];
    const float* Wele = (const float*)d_in[18];
    const float* bele = (const float*)d_in[19];
    const int*   eidx = (const int*)d_in[20];
    float* out = (float*)d_out;

    proj_qkv_kernel<<<dim3(12, 157), 128>>>(x, Wq, bq, Wk, bk, Wv, bv);
    node_edge_kernel<<<NN / 4, 128>>>(ef, eidx, Weq, beq, Wev, bev, Wek, bek,
                                      Wel, bel, Wele, bele, out + NN * 64);
    out_gemm_kernel<<<157, 256>>>(Wlin, blin, out);
}